// round 4
// baseline (speedup 1.0000x reference)
#include <cuda_runtime.h>
#include <cstdint>

// Shapes (fixed by the problem)
#define BT   6          // b*t = 2*3
#define NN   4096       // nodes
#define DD   64         // di = do = de = 64
#define WC   8192       // 2*64*64 hypernet weight cols per node

typedef unsigned long long u64;

// Scratch (device globals — no allocations allowed)
__device__ float g_E   [BT * NN * DD];    // layernormed embeddings
__device__ float g_mii [BT * NN];         // ||e_row||^2 (softmax shift)
__device__ float g_W   [(size_t)NN * WC]; // per-node hypernet weights, 134 MB
__device__ float g_xg2 [BT * NN * DD];    // attention output
__device__ float g_bias[BT * DD];         // per-(b,t) bias

#define FMA2(d, a, b, c) asm("fma.rn.f32x2 %0, %1, %2, %3;" : "=l"(d) : "l"(a), "l"(b), "l"(c))

__device__ __forceinline__ u64 dup2(float v) {
    u64 r;
    asm("mov.b64 %0, {%1, %1};" : "=l"(r) : "f"(v));
    return r;
}
__device__ __forceinline__ float2 unpack2(u64 v) {
    float lo, hi;
    asm("mov.b64 {%0, %1}, %2;" : "=f"(lo), "=f"(hi) : "l"(v));
    return make_float2(lo, hi);
}

// ---------------------------------------------------------------------------
// K1: E[bt,n,:] = LayerNorm(node_emb[n,:] + time_emb[bt,:]); also g_mii=||E||^2
// ---------------------------------------------------------------------------
__global__ __launch_bounds__(256) void k_ln(
    const float* __restrict__ node_emb, const float* __restrict__ time_emb,
    const float* __restrict__ gamma, const float* __restrict__ beta)
{
    int row  = blockIdx.x * 8 + (threadIdx.x >> 5);
    int lane = threadIdx.x & 31;
    if (row >= BT * NN) return;
    int bt = row >> 12;
    int n  = row & (NN - 1);

    float e0 = node_emb[n * DD + lane]      + time_emb[bt * DD + lane];
    float e1 = node_emb[n * DD + 32 + lane] + time_emb[bt * DD + 32 + lane];
    float s  = e0 + e1;
    float s2 = e0 * e0 + e1 * e1;
    #pragma unroll
    for (int off = 16; off; off >>= 1) {
        s  += __shfl_xor_sync(0xffffffffu, s,  off);
        s2 += __shfl_xor_sync(0xffffffffu, s2, off);
    }
    float mu  = s * (1.0f / 64.0f);
    float var = s2 * (1.0f / 64.0f) - mu * mu;
    float rs  = rsqrtf(var + 1e-12f);
    float o0 = (e0 - mu) * rs * gamma[lane]      + beta[lane];
    float o1 = (e1 - mu) * rs * gamma[32 + lane] + beta[32 + lane];
    g_E[row * DD + lane]      = o0;
    g_E[row * DD + 32 + lane] = o1;

    float q2 = o0 * o0 + o1 * o1;
    #pragma unroll
    for (int off = 16; off; off >>= 1)
        q2 += __shfl_xor_sync(0xffffffffu, q2, off);
    if (lane == 0) g_mii[row] = q2;
}

// ---------------------------------------------------------------------------
// K2: bias[bt,o] = time_emb[bt,:] . bias_pool[:,o]
// ---------------------------------------------------------------------------
__global__ void k_bias(const float* __restrict__ time_emb,
                       const float* __restrict__ bias_pool)
{
    int bt = blockIdx.x, o = threadIdx.x;
    float s = 0.f;
    #pragma unroll
    for (int d = 0; d < DD; d++) s += time_emb[bt * DD + d] * bias_pool[d * DD + o];
    g_bias[bt * DD + o] = s;
}

// ---------------------------------------------------------------------------
// K3: W[n, c] = node_emb[n,:] @ weights_pool[:, c]   (4096x64)@(64x8192)
// ---------------------------------------------------------------------------
__global__ __launch_bounds__(256) void k_wgemm(
    const float* __restrict__ A, const float* __restrict__ Bm)
{
    __shared__ float As[64][128];
    __shared__ float Bs[64][64];
    int n0 = blockIdx.y * 128;
    int c0 = blockIdx.x * 64;
    int tid = threadIdx.x;

    #pragma unroll
    for (int p = 0; p < 8; p++) {
        int idx = p * 256 + tid;
        int r   = idx >> 4;
        int c4  = idx & 15;
        float4 v = ((const float4*)A)[(size_t)(n0 + r) * 16 + c4];
        As[c4 * 4 + 0][r] = v.x;
        As[c4 * 4 + 1][r] = v.y;
        As[c4 * 4 + 2][r] = v.z;
        As[c4 * 4 + 3][r] = v.w;
    }
    #pragma unroll
    for (int p = 0; p < 4; p++) {
        int idx = p * 256 + tid;
        int r   = idx >> 4;
        int c4  = idx & 15;
        ((float4*)&Bs[r][0])[c4] = ((const float4*)(Bm + (size_t)r * WC + c0))[c4];
    }
    __syncthreads();

    int tx = tid & 15;
    int ty = tid >> 4;
    float acc[8][4];
    #pragma unroll
    for (int i = 0; i < 8; i++)
        #pragma unroll
        for (int j = 0; j < 4; j++) acc[i][j] = 0.f;

    #pragma unroll
    for (int k = 0; k < 64; k++) {
        float a[8], b[4];
        *(float4*)&a[0] = *(const float4*)&As[k][ty * 8 + 0];
        *(float4*)&a[4] = *(const float4*)&As[k][ty * 8 + 4];
        *(float4*)&b[0] = *(const float4*)&Bs[k][tx * 4];
        #pragma unroll
        for (int i = 0; i < 8; i++)
            #pragma unroll
            for (int j = 0; j < 4; j++) acc[i][j] += a[i] * b[j];
    }

    #pragma unroll
    for (int i = 0; i < 8; i++) {
        int n = n0 + ty * 8 + i;
        *(float4*)(g_W + (size_t)n * WC + c0 + tx * 4) =
            make_float4(acc[i][0], acc[i][1], acc[i][2], acc[i][3]);
    }
}

// ---------------------------------------------------------------------------
// K4: attention, register-tiled with fma.rn.f32x2.
//     Block: 64 queries, 128 threads (tq=tid&15 -> 4 queries, tk=tid>>4 -> 8 k / 8 d).
//     Stage A: S = Eq.Ek^T (Eq/Ek transposed [d][q|k] in smem), exp -> Ps.
//     Stage B: acc += P.X (X natural [k][d]).
// ---------------------------------------------------------------------------
struct AttnSmem {
    float Eqs[64][68];   // [d][q]
    float Eks[64][68];   // [d][k]
    float Xs [64][68];   // [k][d]
    float Ps [64][68];   // [k][q]
    float dsm[8][68];    // denominator partials [tk][q]
};
#define ATTN_SMEM_BYTES ((int)sizeof(AttnSmem))

__global__ __launch_bounds__(128) void k_attn(const float* __restrict__ x)
{
    extern __shared__ char smem_raw[];
    AttnSmem& sm = *(AttnSmem*)smem_raw;

    const int tid = threadIdx.x;
    const int tq  = tid & 15;     // owns queries q0 + tq*4 .. +3
    const int tk  = tid >> 4;     // owns k cols tk*8..+7 (A) / d cols tk*8..+7 (B)
    const int bt  = blockIdx.y;
    const int q0  = blockIdx.x * 64;

    const float* Ebt = g_E + (size_t)bt * NN * DD;
    const float* Xbt = x   + (size_t)bt * NN * DD;

    // Load Eq tile transposed: Eqs[d][q]
    #pragma unroll
    for (int it = 0; it < 8; it++) {
        int idx = it * 128 + tid;
        int q   = idx & 63;
        int c4  = idx >> 6;
        float4 v = *(const float4*)(Ebt + (size_t)(q0 + q) * DD + c4 * 4);
        sm.Eqs[c4 * 4 + 0][q] = v.x;
        sm.Eqs[c4 * 4 + 1][q] = v.y;
        sm.Eqs[c4 * 4 + 2][q] = v.z;
        sm.Eqs[c4 * 4 + 3][q] = v.w;
    }

    float mii[4];
    #pragma unroll
    for (int i = 0; i < 4; i++) mii[i] = g_mii[bt * NN + q0 + tq * 4 + i];

    u64 acc2[4][4];      // [q][d-pair]  (d = tk*8 + 2m, 2m+1)
    #pragma unroll
    for (int i = 0; i < 4; i++)
        #pragma unroll
        for (int m = 0; m < 4; m++) acc2[i][m] = 0ull;
    float dsum[4] = {0.f, 0.f, 0.f, 0.f};

    for (int m0 = 0; m0 < NN; m0 += 64) {
        __syncthreads();   // previous stage-B reads of Eks/Xs/Ps done

        // Load Ek tile transposed: Eks[d][k]
        #pragma unroll
        for (int it = 0; it < 8; it++) {
            int idx = it * 128 + tid;
            int k   = idx & 63;
            int c4  = idx >> 6;
            float4 v = *(const float4*)(Ebt + (size_t)(m0 + k) * DD + c4 * 4);
            sm.Eks[c4 * 4 + 0][k] = v.x;
            sm.Eks[c4 * 4 + 1][k] = v.y;
            sm.Eks[c4 * 4 + 2][k] = v.z;
            sm.Eks[c4 * 4 + 3][k] = v.w;
        }
        // Load X tile natural: Xs[k][d]
        #pragma unroll
        for (int it = 0; it < 8; it++) {
            int idx = it * 128 + tid;
            int k   = idx >> 4;
            int c4  = idx & 15;
            *(float4*)&sm.Xs[k][c4 * 4] =
                *(const float4*)(Xbt + (size_t)(m0 + k) * DD + c4 * 4);
        }
        __syncthreads();

        // Stage A: s[4q][8k] over 64 d
        u64 s2[4][4];
        #pragma unroll
        for (int i = 0; i < 4; i++)
            #pragma unroll
            for (int m = 0; m < 4; m++) s2[i][m] = 0ull;

        #pragma unroll 8
        for (int d = 0; d < 64; d++) {
            float4 av = *(const float4*)&sm.Eqs[d][tq * 4];
            ulonglong2 b01 = *(const ulonglong2*)&sm.Eks[d][tk * 8];
            ulonglong2 b23 = *(const ulonglong2*)&sm.Eks[d][tk * 8 + 4];
            u64 a[4];
            a[0] = dup2(av.x); a[1] = dup2(av.y); a[2] = dup2(av.z); a[3] = dup2(av.w);
            #pragma unroll
            for (int i = 0; i < 4; i++) {
                FMA2(s2[i][0], a[i], b01.x, s2[i][0]);
                FMA2(s2[i][1], a[i], b01.y, s2[i][1]);
                FMA2(s2[i][2], a[i], b23.x, s2[i][2]);
                FMA2(s2[i][3], a[i], b23.y, s2[i][3]);
            }
        }

        // exp + denominator partials
        float p[4][8];
        #pragma unroll
        for (int i = 0; i < 4; i++) {
            float dsi = 0.f;
            #pragma unroll
            for (int m = 0; m < 4; m++) {
                float2 sv = unpack2(s2[i][m]);
                float p0 = __expf(sv.x - mii[i]);
                float p1 = __expf(sv.y - mii[i]);
                p[i][2 * m]     = p0;
                p[i][2 * m + 1] = p1;
                dsi += p0 + p1;
            }
            dsum[i] += dsi;
        }
        // store P: Ps[k][q]
        #pragma unroll
        for (int j = 0; j < 8; j++) {
            *(float4*)&sm.Ps[tk * 8 + j][tq * 4] =
                make_float4(p[0][j], p[1][j], p[2][j], p[3][j]);
        }
        __syncthreads();

        // Stage B: acc[4q][8d] += P . X over 64 k
        #pragma unroll 8
        for (int k = 0; k < 64; k++) {
            float4 pv = *(const float4*)&sm.Ps[k][tq * 4];
            ulonglong2 x01 = *(const ulonglong2*)&sm.Xs[k][tk * 8];
            ulonglong2 x23 = *(const ulonglong2*)&sm.Xs[k][tk * 8 + 4];
            u64 a[4];
            a[0] = dup2(pv.x); a[1] = dup2(pv.y); a[2] = dup2(pv.z); a[3] = dup2(pv.w);
            #pragma unroll
            for (int i = 0; i < 4; i++) {
                FMA2(acc2[i][0], a[i], x01.x, acc2[i][0]);
                FMA2(acc2[i][1], a[i], x01.y, acc2[i][1]);
                FMA2(acc2[i][2], a[i], x23.x, acc2[i][2]);
                FMA2(acc2[i][3], a[i], x23.y, acc2[i][3]);
            }
        }
    }

    // denominator reduce across tk
    __syncthreads();
    #pragma unroll
    for (int i = 0; i < 4; i++) sm.dsm[tk][tq * 4 + i] = dsum[i];
    __syncthreads();
    float inv[4];
    #pragma unroll
    for (int i = 0; i < 4; i++) {
        float t = 0.f;
        #pragma unroll
        for (int t8 = 0; t8 < 8; t8++) t += sm.dsm[t8][tq * 4 + i];
        inv[i] = 1.0f / t;
    }

    // write xg2
    #pragma unroll
    for (int i = 0; i < 4; i++) {
        float2 a0 = unpack2(acc2[i][0]);
        float2 a1 = unpack2(acc2[i][1]);
        float2 a2 = unpack2(acc2[i][2]);
        float2 a3 = unpack2(acc2[i][3]);
        float* op = g_xg2 + ((size_t)bt * NN + q0 + tq * 4 + i) * DD + tk * 8;
        *(float4*)op       = make_float4(a0.x * inv[i], a0.y * inv[i],
                                         a1.x * inv[i], a1.y * inv[i]);
        *(float4*)(op + 4) = make_float4(a2.x * inv[i], a2.y * inv[i],
                                         a3.x * inv[i], a3.y * inv[i]);
    }
}

// ---------------------------------------------------------------------------
// K5: out[bt,n,o] = x[bt,n,:].W1[n,:,o] + xg2[bt,n,:].W2[n,:,o] + bias[bt,o]
// ---------------------------------------------------------------------------
__global__ __launch_bounds__(384) void k_apply(const float* __restrict__ x,
                                               float* __restrict__ out)
{
    __shared__ float Ws[WC];
    __shared__ float xs [BT * DD];
    __shared__ float x2s[BT * DD];
    int n = blockIdx.x;
    const float4* Wn = (const float4*)(g_W + (size_t)n * WC);
    for (int i = threadIdx.x; i < WC / 4; i += 384) ((float4*)Ws)[i] = Wn[i];
    for (int i = threadIdx.x; i < BT * 16; i += 384) {
        int bt = i >> 4, c4 = i & 15;
        ((float4*)xs )[i] = ((const float4*)(x     + ((size_t)bt * NN + n) * DD))[c4];
        ((float4*)x2s)[i] = ((const float4*)(g_xg2 + ((size_t)bt * NN + n) * DD))[c4];
    }
    __syncthreads();

    int bt = threadIdx.x / 64;
    int o  = threadIdx.x & 63;
    float s = g_bias[bt * DD + o];
    #pragma unroll
    for (int i = 0; i < DD; i++) s += xs [bt * DD + i] * Ws[i * DD + o];
    #pragma unroll
    for (int i = 0; i < DD; i++) s += x2s[bt * DD + i] * Ws[4096 + i * DD + o];
    out[((size_t)bt * NN + n) * DD + o] = s;
}

// ---------------------------------------------------------------------------
extern "C" void kernel_launch(void* const* d_in, const int* in_sizes, int n_in,
                              void* d_out, int out_size)
{
    const float* x        = (const float*)d_in[0];  // (2,3,4096,64)
    const float* node_emb = (const float*)d_in[1];  // (4096,64)
    const float* time_emb = (const float*)d_in[2];  // (2,3,64)
    const float* wpool    = (const float*)d_in[3];  // (64,2,64,64)
    const float* bpool    = (const float*)d_in[4];  // (64,64)
    const float* gamma    = (const float*)d_in[5];  // (64,)
    const float* beta     = (const float*)d_in[6];  // (64,)
    float* out = (float*)d_out;                     // (2,3,4096,64)

    cudaFuncSetAttribute(k_attn, cudaFuncAttributeMaxDynamicSharedMemorySize,
                         ATTN_SMEM_BYTES);

    k_ln   <<<(BT * NN) / 8, 256>>>(node_emb, time_emb, gamma, beta);
    k_bias <<<BT, DD>>>(time_emb, bpool);
    k_wgemm<<<dim3(WC / 64, NN / 128), 256>>>(node_emb, wpool);
    k_attn <<<dim3(NN / 64, BT), 128, ATTN_SMEM_BYTES>>>(x);
    k_apply<<<NN, 384>>>(x, out);
}

// round 6
// speedup vs baseline: 1.9365x; 1.9365x over previous
#include <cuda_runtime.h>
#include <cuda_bf16.h>
#include <cstdint>

#define BT 6
#define NN 4096
#define DD 64
#define WC 8192

typedef unsigned long long u64;

// Scratch (device globals — no allocations allowed)
__device__ float    g_mii [BT*NN];           // ||e_row||^2 (softmax shift)
__device__ uint32_t g_Eh32[BT*NN*32];        // E hi, bf16x2 packed (32 u32/row)
__device__ uint32_t g_El32[BT*NN*32];        // E lo
__device__ uint32_t g_Xth [BT*DD*(NN/2)];    // X^T hi: [bt*64+d][k/2] bf16x2
__device__ uint32_t g_Xtl [BT*DD*(NN/2)];    // X^T lo
__device__ float    g_W   [(size_t)NN*WC];   // hypernet weights, 134 MB
__device__ float    g_xg2 [BT*NN*DD];        // attention output (normalized)
__device__ float    g_bias[BT*DD];

// ---------------- helpers ----------------
#define FMA2(d, a, b, c) asm("fma.rn.f32x2 %0, %1, %2, %3;" : "=l"(d) : "l"(a), "l"(b), "l"(c))
__device__ __forceinline__ u64 dup2(float v) {
    u64 r; asm("mov.b64 %0, {%1, %1};" : "=l"(r) : "f"(v)); return r;
}
__device__ __forceinline__ u64 pack2(float a, float b) {
    u64 r; asm("mov.b64 %0, {%1, %2};" : "=l"(r) : "f"(a), "f"(b)); return r;
}
__device__ __forceinline__ float2 unpack2(u64 v) {
    float a, b; asm("mov.b64 {%0, %1}, %2;" : "=f"(a), "=f"(b) : "l"(v));
    return make_float2(a, b);
}
__device__ __forceinline__ uint32_t pkbf(float a, float b) {
    __nv_bfloat162 t; t.x = __float2bfloat16(a); t.y = __float2bfloat16(b);
    return *reinterpret_cast<uint32_t*>(&t);
}
// hi/lo bf16 split of a float pair
__device__ __forceinline__ void split2(float a, float b, uint32_t& hi, uint32_t& lo) {
    __nv_bfloat16 ha = __float2bfloat16(a), hb = __float2bfloat16(b);
    __nv_bfloat162 hp; hp.x = ha; hp.y = hb;
    hi = *reinterpret_cast<uint32_t*>(&hp);
    lo = pkbf(a - __bfloat162float(ha), b - __bfloat162float(hb));
}
// warp MMA: D(16x8,f32) += A(16x16,bf16) * B(16x8,bf16,col-major)
__device__ __forceinline__ void mma16816(float* c, const uint32_t* a, uint32_t b0, uint32_t b1) {
    asm volatile(
        "mma.sync.aligned.m16n8k16.row.col.f32.bf16.bf16.f32 "
        "{%0,%1,%2,%3}, {%4,%5,%6,%7}, {%8,%9}, {%0,%1,%2,%3};"
        : "+f"(c[0]), "+f"(c[1]), "+f"(c[2]), "+f"(c[3])
        : "r"(a[0]), "r"(a[1]), "r"(a[2]), "r"(a[3]), "r"(b0), "r"(b1));
}
__device__ __forceinline__ void cpa16(void* dst, const void* src) {
    uint32_t d = (uint32_t)__cvta_generic_to_shared(dst);
    asm volatile("cp.async.ca.shared.global [%0], [%1], 16;" :: "r"(d), "l"(src));
}
#define CP_COMMIT() asm volatile("cp.async.commit_group;" ::: "memory")
#define CP_WAIT1()  asm volatile("cp.async.wait_group 1;" ::: "memory")

// ---------------- K1: LayerNorm -> bf16 hi/lo + mii ----------------
__global__ __launch_bounds__(256) void k_ln(
    const float* __restrict__ ne, const float* __restrict__ te,
    const float* __restrict__ gamma, const float* __restrict__ beta)
{
    int row = blockIdx.x * 8 + (threadIdx.x >> 5);
    int lane = threadIdx.x & 31;
    int bt = row >> 12, n = row & (NN - 1);
    float2 nv = *(const float2*)(ne + n * DD + 2 * lane);
    float2 tv = *(const float2*)(te + bt * DD + 2 * lane);
    float e0 = nv.x + tv.x, e1 = nv.y + tv.y;
    float s = e0 + e1, s2 = e0 * e0 + e1 * e1;
    #pragma unroll
    for (int o = 16; o; o >>= 1) {
        s  += __shfl_xor_sync(~0u, s,  o);
        s2 += __shfl_xor_sync(~0u, s2, o);
    }
    float mu = s * (1.f / 64.f), var = s2 * (1.f / 64.f) - mu * mu;
    float rs = rsqrtf(var + 1e-12f);
    float o0 = (e0 - mu) * rs * gamma[2 * lane]     + beta[2 * lane];
    float o1 = (e1 - mu) * rs * gamma[2 * lane + 1] + beta[2 * lane + 1];
    uint32_t hi, lo;
    split2(o0, o1, hi, lo);
    g_Eh32[row * 32 + lane] = hi;
    g_El32[row * 32 + lane] = lo;
    float q2 = o0 * o0 + o1 * o1;
    #pragma unroll
    for (int o = 16; o; o >>= 1) q2 += __shfl_xor_sync(~0u, q2, o);
    if (lane == 0) g_mii[row] = q2;
}

// ---------------- K1b: X -> X^T bf16 hi/lo ----------------
__global__ __launch_bounds__(256) void k_xsplit(const float* __restrict__ x)
{
    __shared__ float t[64][65];
    int bt = blockIdx.y, k0 = blockIdx.x * 64;
    for (int i = threadIdx.x; i < 4096; i += 256)
        t[i >> 6][i & 63] = x[((size_t)bt * NN + k0 + (i >> 6)) * DD + (i & 63)];
    __syncthreads();
    for (int i = threadIdx.x; i < 2048; i += 256) {
        int d = i >> 5, c2 = i & 31;
        uint32_t hi, lo;
        split2(t[c2 * 2][d], t[c2 * 2 + 1][d], hi, lo);
        size_t gi = (size_t)(bt * DD + d) * (NN / 2) + k0 / 2 + c2;
        g_Xth[gi] = hi;
        g_Xtl[gi] = lo;
    }
}

// ---------------- K2: bias ----------------
__global__ void k_bias(const float* __restrict__ te, const float* __restrict__ bp)
{
    int bt = blockIdx.x, o = threadIdx.x;
    float s = 0.f;
    #pragma unroll
    for (int d = 0; d < DD; d++) s += te[bt * DD + d] * bp[d * DD + o];
    g_bias[bt * DD + o] = s;
}

// ---------------- K3: W = node_emb @ weights_pool (f32x2 packed FMA) --------
__global__ __launch_bounds__(256) void k_wgemm(
    const float* __restrict__ A, const float* __restrict__ Bm)
{
    __shared__ float As[64][128];
    __shared__ float Bs[64][64];
    int n0 = blockIdx.y * 128, c0 = blockIdx.x * 64, tid = threadIdx.x;
    #pragma unroll
    for (int p = 0; p < 8; p++) {
        int idx = p * 256 + tid, r = idx >> 4, c4 = idx & 15;
        float4 v = ((const float4*)A)[(size_t)(n0 + r) * 16 + c4];
        As[c4 * 4 + 0][r] = v.x; As[c4 * 4 + 1][r] = v.y;
        As[c4 * 4 + 2][r] = v.z; As[c4 * 4 + 3][r] = v.w;
    }
    #pragma unroll
    for (int p = 0; p < 4; p++) {
        int idx = p * 256 + tid, r = idx >> 4, c4 = idx & 15;
        ((float4*)&Bs[r][0])[c4] = ((const float4*)(Bm + (size_t)r * WC + c0))[c4];
    }
    __syncthreads();
    int tx = tid & 15, ty = tid >> 4;
    u64 acc2[8][2];
    #pragma unroll
    for (int i = 0; i < 8; i++) { acc2[i][0] = 0ull; acc2[i][1] = 0ull; }
    #pragma unroll
    for (int k = 0; k < 64; k++) {
        float a[8];
        *(float4*)&a[0] = *(const float4*)&As[k][ty * 8];
        *(float4*)&a[4] = *(const float4*)&As[k][ty * 8 + 4];
        float4 b4 = *(const float4*)&Bs[k][tx * 4];
        u64 b01 = pack2(b4.x, b4.y), b23 = pack2(b4.z, b4.w);
        #pragma unroll
        for (int i = 0; i < 8; i++) {
            u64 ai = dup2(a[i]);
            FMA2(acc2[i][0], ai, b01, acc2[i][0]);
            FMA2(acc2[i][1], ai, b23, acc2[i][1]);
        }
    }
    #pragma unroll
    for (int i = 0; i < 8; i++) {
        float2 v0 = unpack2(acc2[i][0]), v1 = unpack2(acc2[i][1]);
        *(float4*)(g_W + (size_t)(n0 + ty * 8 + i) * WC + c0 + tx * 4) =
            make_float4(v0.x, v0.y, v1.x, v1.y);
    }
}

// ---------------- K4: HMMA attention (bf16 hi/lo split, 3 passes) ----------
// Block: 64 queries (warp w owns rows q0+w*16..+15), all 4096 keys in 128
// subtiles of 32. Double-buffered cp.async smem tiles. P stays in registers
// (C-fragment of S == A-fragment of PV).
__global__ __launch_bounds__(128) void k_attn_mma()
{
    __shared__ uint32_t sEh[2][32][36], sEl[2][32][36];   // keys x dim-pairs (+pad)
    __shared__ uint32_t sXh[2][64][20], sXl[2][64][20];   // dims x key-pairs (+pad)

    const int tid = threadIdx.x, w = tid >> 5, l = tid & 31;
    const int tig = l & 3, gr = l >> 2;
    const int bt = blockIdx.y;
    const int q0 = blockIdx.x * 64;

    // Q fragments (hi/lo), one m16 tile per warp
    const size_t qrow = (size_t)(bt * NN + q0 + w * 16 + gr);
    uint32_t Qh[4][4], Ql[4][4];
    #pragma unroll
    for (int kc = 0; kc < 4; kc++) {
        int c0 = kc * 8 + tig, c1 = kc * 8 + 4 + tig;
        Qh[kc][0] = g_Eh32[qrow * 32 + c0];
        Qh[kc][1] = g_Eh32[(qrow + 8) * 32 + c0];
        Qh[kc][2] = g_Eh32[qrow * 32 + c1];
        Qh[kc][3] = g_Eh32[(qrow + 8) * 32 + c1];
        Ql[kc][0] = g_El32[qrow * 32 + c0];
        Ql[kc][1] = g_El32[(qrow + 8) * 32 + c0];
        Ql[kc][2] = g_El32[qrow * 32 + c1];
        Ql[kc][3] = g_El32[(qrow + 8) * 32 + c1];
    }
    const float mii0 = g_mii[qrow];
    const float mii1 = g_mii[qrow + 8];

    float acc[8][4];
    #pragma unroll
    for (int i = 0; i < 8; i++)
        #pragma unroll
        for (int j = 0; j < 4; j++) acc[i][j] = 0.f;
    float den0 = 0.f, den1 = 0.f;

    auto prefetch = [&](int t) {
        if (t < 128) {
            int b = t & 1, m = t * 32;
            #pragma unroll
            for (int i = tid; i < 256; i += 128) {
                int r = i >> 3, c = (i & 7) << 2;
                size_t g = (size_t)(bt * NN + m + r) * 32 + c;
                cpa16(&sEh[b][r][c], g_Eh32 + g);
                cpa16(&sEl[b][r][c], g_El32 + g);
            }
            #pragma unroll
            for (int i = tid; i < 256; i += 128) {
                int r = i >> 2, c = (i & 3) << 2;
                size_t g = (size_t)(bt * DD + r) * (NN / 2) + (m >> 1) + c;
                cpa16(&sXh[b][r][c], g_Xth + g);
                cpa16(&sXl[b][r][c], g_Xtl + g);
            }
        }
        CP_COMMIT();
    };

    prefetch(0);

    for (int t = 0; t < 128; t++) {
        prefetch(t + 1);
        CP_WAIT1();
        __syncthreads();

        const uint32_t (*Eh)[36] = sEh[t & 1];
        const uint32_t (*El)[36] = sEl[t & 1];
        const uint32_t (*Xh)[20] = sXh[t & 1];
        const uint32_t (*Xl)[20] = sXl[t & 1];

        // S = Eq . Ek^T  (16q x 32k per warp), 3 split passes
        float sacc[4][4];
        #pragma unroll
        for (int i = 0; i < 4; i++)
            #pragma unroll
            for (int j = 0; j < 4; j++) sacc[i][j] = 0.f;
        #pragma unroll
        for (int kc = 0; kc < 4; kc++) {
            #pragma unroll
            for (int nt = 0; nt < 4; nt++) {
                const uint32_t* er = Eh[nt * 8 + gr];
                const uint32_t* lr = El[nt * 8 + gr];
                uint32_t bh0 = er[kc * 8 + tig], bh1 = er[kc * 8 + 4 + tig];
                uint32_t bl0 = lr[kc * 8 + tig], bl1 = lr[kc * 8 + 4 + tig];
                mma16816(sacc[nt], Qh[kc], bh0, bh1);
                mma16816(sacc[nt], Qh[kc], bl0, bl1);
                mma16816(sacc[nt], Ql[kc], bh0, bh1);
            }
        }

        // exp + repack C-frag -> A-frag (P hi/lo)
        uint32_t ph[2][4], pl[2][4];
        #pragma unroll
        for (int nt = 0; nt < 4; nt++) {
            float p0 = __expf(sacc[nt][0] - mii0);
            float p1 = __expf(sacc[nt][1] - mii0);
            float p2 = __expf(sacc[nt][2] - mii1);
            float p3 = __expf(sacc[nt][3] - mii1);
            den0 += p0 + p1;
            den1 += p2 + p3;
            uint32_t h01, l01, h23, l23;
            split2(p0, p1, h01, l01);
            split2(p2, p3, h23, l23);
            int kc2 = nt >> 1;
            if ((nt & 1) == 0) {
                ph[kc2][0] = h01; ph[kc2][1] = h23;
                pl[kc2][0] = l01; pl[kc2][1] = l23;
            } else {
                ph[kc2][2] = h01; ph[kc2][3] = h23;
                pl[kc2][2] = l01; pl[kc2][3] = l23;
            }
        }

        // acc += P . X^T  (16q x 64d), 3 split passes
        #pragma unroll
        for (int kc2 = 0; kc2 < 2; kc2++) {
            #pragma unroll
            for (int dt = 0; dt < 8; dt++) {
                const uint32_t* xr = Xh[dt * 8 + gr];
                const uint32_t* yr = Xl[dt * 8 + gr];
                uint32_t bh0 = xr[kc2 * 8 + tig], bh1 = xr[kc2 * 8 + 4 + tig];
                uint32_t bl0 = yr[kc2 * 8 + tig], bl1 = yr[kc2 * 8 + 4 + tig];
                mma16816(acc[dt], ph[kc2], bh0, bh1);
                mma16816(acc[dt], ph[kc2], bl0, bl1);
                mma16816(acc[dt], pl[kc2], bh0, bh1);
            }
        }
        __syncthreads();
    }

    // row-sum reduce across the quad, normalize, store
    den0 += __shfl_xor_sync(~0u, den0, 1);
    den0 += __shfl_xor_sync(~0u, den0, 2);
    den1 += __shfl_xor_sync(~0u, den1, 1);
    den1 += __shfl_xor_sync(~0u, den1, 2);
    float i0 = 1.f / den0, i1 = 1.f / den1;
    #pragma unroll
    for (int dt = 0; dt < 8; dt++) {
        *(float2*)(g_xg2 + qrow * 64 + dt * 8 + 2 * tig) =
            make_float2(acc[dt][0] * i0, acc[dt][1] * i0);
        *(float2*)(g_xg2 + (qrow + 8) * 64 + dt * 8 + 2 * tig) =
            make_float2(acc[dt][2] * i1, acc[dt][3] * i1);
    }
}

// ---------------- K5: apply hypernet weights ----------------
__global__ __launch_bounds__(384) void k_apply(const float* __restrict__ x,
                                               float* __restrict__ out)
{
    __shared__ float Ws[WC];
    __shared__ float xs[BT * DD];
    __shared__ float x2s[BT * DD];
    int n = blockIdx.x;
    const float4* Wn = (const float4*)(g_W + (size_t)n * WC);
    for (int i = threadIdx.x; i < WC / 4; i += 384) ((float4*)Ws)[i] = Wn[i];
    for (int i = threadIdx.x; i < BT * 16; i += 384) {
        int bt = i >> 4, c4 = i & 15;
        size_t base = ((size_t)bt * NN + n) * DD;
        ((float4*)xs)[i]  = ((const float4*)(x + base))[c4];
        ((float4*)x2s)[i] = ((const float4*)(g_xg2 + base))[c4];
    }
    __syncthreads();
    int bt = threadIdx.x / 64, o = threadIdx.x & 63;
    float s = g_bias[bt * DD + o];
    #pragma unroll
    for (int i = 0; i < DD; i++) s += xs[bt * DD + i] * Ws[i * DD + o];
    #pragma unroll
    for (int i = 0; i < DD; i++) s += x2s[bt * DD + i] * Ws[4096 + i * DD + o];
    out[((size_t)bt * NN + n) * DD + o] = s;
}

// ---------------------------------------------------------------------------
extern "C" void kernel_launch(void* const* d_in, const int* in_sizes, int n_in,
                              void* d_out, int out_size)
{
    const float* x     = (const float*)d_in[0];
    const float* ne    = (const float*)d_in[1];
    const float* te    = (const float*)d_in[2];
    const float* wpool = (const float*)d_in[3];
    const float* bpool = (const float*)d_in[4];
    const float* gamma = (const float*)d_in[5];
    const float* beta  = (const float*)d_in[6];
    float* out = (float*)d_out;

    k_ln      <<<(BT * NN) / 8, 256>>>(ne, te, gamma, beta);
    k_xsplit  <<<dim3(NN / 64, BT), 256>>>(x);
    k_bias    <<<BT, DD>>>(te, bpool);
    k_wgemm   <<<dim3(WC / 64, NN / 128), 256>>>(ne, wpool);
    k_attn_mma<<<dim3(NN / 64, BT), 128>>>();
    k_apply   <<<NN, 384>>>(x, out);
}